// round 1
// baseline (speedup 1.0000x reference)
#include <cuda_runtime.h>
#include <math.h>

// ---------------- problem constants (shapes fixed by the dataset) ----------
#define FIN   256
#define HC1   128      // H1*C1
#define H1    4
#define C1    32
#define C2    16
#define MAXN  50016
#define MAXTOT 861000  // E + N upper bound

#define EPSV 1e-16f

// ---------------- device scratch (no allocations allowed) ------------------
__device__ int   g_deg[MAXN + 1];
__device__ int   g_fill[MAXN + 1];
__device__ int   g_rowptr[MAXN + 1];
__device__ int   g_csr[MAXTOT];
__device__ float g_h1[MAXN * HC1];
__device__ float g_as1[MAXN * H1];
__device__ float g_ad1[MAXN * H1];
__device__ float g_hact[MAXN * HC1];
__device__ float g_h2[MAXN * C2];
__device__ float g_as2[MAXN];
__device__ float g_ad2[MAXN];

// ---------------- helpers --------------------------------------------------
__device__ __forceinline__ float lrelu(float x) { return x > 0.f ? x : 0.2f * x; }

// ---------------- CSR build ------------------------------------------------
__global__ void k_zero(int N) {
    int t = blockIdx.x * blockDim.x + threadIdx.x;
    if (t <= N) { g_deg[t] = 0; g_fill[t] = 0; }
}

__global__ void k_hist(const int* __restrict__ ei, int E, int N) {
    int t = blockIdx.x * blockDim.x + threadIdx.x;
    int tot = E + N;
    if (t >= tot) return;
    int dst = (t < E) ? ei[E + t] : (t - E);
    atomicAdd(&g_deg[dst], 1);
}

// single-block exclusive scan of g_deg[0..N) -> g_rowptr[0..N]
__global__ void k_scan(int N) {
    __shared__ int part[1024];
    int tid = threadIdx.x;
    int chunk = (N + 1023) / 1024;
    int start = tid * chunk;
    int s = 0;
    for (int i = 0; i < chunk; i++) {
        int idx = start + i;
        if (idx < N) s += g_deg[idx];
    }
    part[tid] = s;
    __syncthreads();
    // Hillis-Steele inclusive scan
    for (int o = 1; o < 1024; o <<= 1) {
        int v = (tid >= o) ? part[tid - o] : 0;
        __syncthreads();
        part[tid] += v;
        __syncthreads();
    }
    int run = (tid == 0) ? 0 : part[tid - 1];
    for (int i = 0; i < chunk; i++) {
        int idx = start + i;
        if (idx < N) { g_rowptr[idx] = run; run += g_deg[idx]; }
    }
    if (tid == 1023) g_rowptr[N] = part[1023];
}

__global__ void k_scatter(const int* __restrict__ ei, int E, int N) {
    int t = blockIdx.x * blockDim.x + threadIdx.x;
    int tot = E + N;
    if (t >= tot) return;
    int src, dst;
    if (t < E) { src = ei[t]; dst = ei[E + t]; }
    else       { src = t - E; dst = t - E; }
    int pos = atomicAdd(&g_fill[dst], 1);
    g_csr[g_rowptr[dst] + pos] = src;
}

// ---------------- GEMM1: h1 = x @ W1  ([M,256] x [256,128]) ----------------
__global__ void k_gemm1(const float* __restrict__ A, const float* __restrict__ B, int M) {
    // BM=128, BN=128, BK=8, 256 threads, 8x8 per thread
    __shared__ float As[8][128];
    __shared__ float Bs[8][128];
    const int K = FIN, Ncol = HC1;
    int block_row = blockIdx.x * 128;
    int tx = threadIdx.x;
    int trow = (tx / 16) * 8;
    int tcol = (tx % 16) * 8;
    float acc[8][8];
#pragma unroll
    for (int i = 0; i < 8; i++)
#pragma unroll
        for (int j = 0; j < 8; j++) acc[i][j] = 0.f;

    for (int k0 = 0; k0 < K; k0 += 8) {
        // load A tile: 128 rows x 8 cols, float4 per thread
        {
            int r  = tx >> 1;
            int kk = (tx & 1) * 4;
            int grow = block_row + r;
            float4 v = make_float4(0.f, 0.f, 0.f, 0.f);
            if (grow < M) v = *reinterpret_cast<const float4*>(&A[(long)grow * K + k0 + kk]);
            As[kk + 0][r] = v.x; As[kk + 1][r] = v.y;
            As[kk + 2][r] = v.z; As[kk + 3][r] = v.w;
        }
        // load B tile: 8 rows x 128 cols, float4 coalesced
        {
            int r = tx >> 5;
            int c = (tx * 4) & 127;
            float4 v = *reinterpret_cast<const float4*>(&B[(k0 + r) * Ncol + c]);
            *reinterpret_cast<float4*>(&Bs[r][c]) = v;
        }
        __syncthreads();
#pragma unroll
        for (int kk = 0; kk < 8; kk++) {
            float a[8], b[8];
            *reinterpret_cast<float4*>(&a[0]) = *reinterpret_cast<const float4*>(&As[kk][trow]);
            *reinterpret_cast<float4*>(&a[4]) = *reinterpret_cast<const float4*>(&As[kk][trow + 4]);
            *reinterpret_cast<float4*>(&b[0]) = *reinterpret_cast<const float4*>(&Bs[kk][tcol]);
            *reinterpret_cast<float4*>(&b[4]) = *reinterpret_cast<const float4*>(&Bs[kk][tcol + 4]);
#pragma unroll
            for (int i = 0; i < 8; i++)
#pragma unroll
                for (int j = 0; j < 8; j++) acc[i][j] = fmaf(a[i], b[j], acc[i][j]);
        }
        __syncthreads();
    }
#pragma unroll
    for (int i = 0; i < 8; i++) {
        int grow = block_row + trow + i;
        if (grow < M) {
            *reinterpret_cast<float4*>(&g_h1[(long)grow * HC1 + tcol])     = *reinterpret_cast<float4*>(&acc[i][0]);
            *reinterpret_cast<float4*>(&g_h1[(long)grow * HC1 + tcol + 4]) = *reinterpret_cast<float4*>(&acc[i][4]);
        }
    }
}

// ---------------- per-node attention logits, layer 1 -----------------------
__global__ void k_alpha1(const float* __restrict__ a_s, const float* __restrict__ a_d, int N) {
    int w = (blockIdx.x * blockDim.x + threadIdx.x) >> 5;
    int lane = threadIdx.x & 31;
    if (w >= N) return;
#pragma unroll
    for (int h = 0; h < H1; h++) {
        float v = g_h1[(long)w * HC1 + h * C1 + lane];
        float s = v * a_s[h * C1 + lane];
        float d = v * a_d[h * C1 + lane];
#pragma unroll
        for (int o = 16; o; o >>= 1) {
            s += __shfl_xor_sync(0xffffffffu, s, o);
            d += __shfl_xor_sync(0xffffffffu, d, o);
        }
        if (lane == 0) { g_as1[w * H1 + h] = s; g_ad1[w * H1 + h] = d; }
    }
}

// ---------------- attention + aggregate, layer 1 ----------------------------
// one warp per (node, head); lanes = channels (C1 = 32)
__global__ void k_attn1(const float* __restrict__ b1, int N) {
    int w = (blockIdx.x * blockDim.x + threadIdx.x) >> 5;
    int lane = threadIdx.x & 31;
    if (w >= N * H1) return;
    int node = w >> 2;
    int head = w & 3;
    int beg = g_rowptr[node], end = g_rowptr[node + 1];
    float adv = g_ad1[node * H1 + head];

    // pass 1: max
    float m = -1e30f;
    for (int i = beg + lane; i < end; i += 32) {
        float e = lrelu(g_as1[g_csr[i] * H1 + head] + adv);
        m = fmaxf(m, e);
    }
#pragma unroll
    for (int o = 16; o; o >>= 1) m = fmaxf(m, __shfl_xor_sync(0xffffffffu, m, o));

    // pass 2: exp/sum/accumulate (chunked loads, shfl broadcast)
    float acc = 0.f, ssum = 0.f;
    for (int base = beg; base < end; base += 32) {
        int i = base + lane;
        int src_l = 0;
        float e_l = 0.f;
        if (i < end) {
            src_l = g_csr[i];
            e_l = lrelu(g_as1[src_l * H1 + head] + adv);
        }
        int cnt = min(32, end - base);
        for (int j = 0; j < cnt; j++) {
            int src  = __shfl_sync(0xffffffffu, src_l, j);
            float e  = __shfl_sync(0xffffffffu, e_l, j);
            float wt = __expf(e - m);
            ssum += wt;
            acc = fmaf(g_h1[(long)src * HC1 + head * C1 + lane], wt, acc);
        }
    }
    float o = acc / (ssum + EPSV) + b1[head * C1 + lane];
    // ELU
    g_hact[(long)node * HC1 + head * C1 + lane] = o > 0.f ? o : (__expf(o) - 1.f);
}

// ---------------- GEMM2 + layer-2 logits ------------------------------------
// warp handles 2 nodes; lanes: sub = lane>>4, c = lane&15
__global__ void k_gemm2(const float* __restrict__ W2, const float* __restrict__ a_s2,
                        const float* __restrict__ a_d2, int N) {
    __shared__ float w2s[HC1 * C2];
    int tx = threadIdx.x;
#pragma unroll
    for (int i = tx; i < HC1 * C2; i += 256) w2s[i] = W2[i];
    __syncthreads();

    int warp = (blockIdx.x * blockDim.x + tx) >> 5;
    int lane = tx & 31;
    int sub = lane >> 4, c = lane & 15;
    int node = warp * 2 + sub;
    int node_c = node < N ? node : (N - 1);

    const float* row = &g_hact[(long)node_c * HC1];
    float acc = 0.f;
#pragma unroll 8
    for (int k = 0; k < HC1; k++) acc = fmaf(row[k], w2s[k * C2 + c], acc);

    float s = acc * a_s2[c];
    float d = acc * a_d2[c];
#pragma unroll
    for (int o = 8; o; o >>= 1) {
        s += __shfl_xor_sync(0xffffffffu, s, o);
        d += __shfl_xor_sync(0xffffffffu, d, o);
    }
    if (node < N) {
        g_h2[node * C2 + c] = acc;
        if (c == 0) { g_as2[node] = s; g_ad2[node] = d; }
    }
}

// ---------------- attention + aggregate, layer 2 ----------------------------
// one warp per node; 16 channels
__global__ void k_attn2(const float* __restrict__ b2, float* __restrict__ out, int N) {
    int w = (blockIdx.x * blockDim.x + threadIdx.x) >> 5;
    int lane = threadIdx.x & 31;
    if (w >= N) return;
    int node = w;
    int beg = g_rowptr[node], end = g_rowptr[node + 1];
    float adv = g_ad2[node];

    float m = -1e30f;
    for (int i = beg + lane; i < end; i += 32) {
        float e = lrelu(g_as2[g_csr[i]] + adv);
        m = fmaxf(m, e);
    }
#pragma unroll
    for (int o = 16; o; o >>= 1) m = fmaxf(m, __shfl_xor_sync(0xffffffffu, m, o));

    float acc = 0.f, ssum = 0.f;
    int cc = lane & 15;
    for (int base = beg; base < end; base += 32) {
        int i = base + lane;
        int src_l = 0;
        float e_l = 0.f;
        if (i < end) {
            src_l = g_csr[i];
            e_l = lrelu(g_as2[src_l] + adv);
        }
        int cnt = min(32, end - base);
        for (int j = 0; j < cnt; j++) {
            int src  = __shfl_sync(0xffffffffu, src_l, j);
            float e  = __shfl_sync(0xffffffffu, e_l, j);
            float wt = __expf(e - m);
            ssum += wt;
            acc = fmaf(g_h2[src * C2 + cc], wt, acc);
        }
    }
    if (lane < 16) {
        out[node * C2 + lane] = acc / (ssum + EPSV) + b2[lane];
    }
}

// ---------------- launch -----------------------------------------------------
extern "C" void kernel_launch(void* const* d_in, const int* in_sizes, int n_in,
                              void* d_out, int out_size) {
    const float* x   = (const float*)d_in[0];
    const int*   ei  = (const int*)d_in[1];
    const float* W1  = (const float*)d_in[2];
    const float* a_s1 = (const float*)d_in[3];
    const float* a_d1 = (const float*)d_in[4];
    const float* b1  = (const float*)d_in[5];
    const float* W2  = (const float*)d_in[6];
    const float* a_s2 = (const float*)d_in[7];
    const float* a_d2 = (const float*)d_in[8];
    const float* b2  = (const float*)d_in[9];
    float* out = (float*)d_out;

    const int Fin = in_sizes[2] / in_sizes[5];       // 32768 / 128 = 256
    const int N   = in_sizes[0] / Fin;               // 50000
    const int E   = in_sizes[1] / 2;                 // 800000
    const int TOT = E + N;

    // CSR build
    k_zero<<<(N + 256) / 256, 256>>>(N);
    k_hist<<<(TOT + 255) / 256, 256>>>(ei, E, N);
    k_scan<<<1, 1024>>>(N);
    k_scatter<<<(TOT + 255) / 256, 256>>>(ei, E, N);

    // layer 1
    k_gemm1<<<(N + 127) / 128, 256>>>(x, W1, N);
    k_alpha1<<<(N * 32 + 255) / 256, 256>>>(a_s1, a_d1, N);
    k_attn1<<<(N * H1 * 32 + 255) / 256, 256>>>(b1, N);

    // layer 2
    k_gemm2<<<((N + 1) / 2 * 32 + 255) / 256, 256>>>(W2, a_s2, a_d2, N);
    k_attn2<<<(N * 32 + 255) / 256, 256>>>(b2, out, N);
}